// round 1
// baseline (speedup 1.0000x reference)
#include <cuda_runtime.h>
#include <math.h>

#define B      8
#define DM     4096
#define NH     32
#define NKV    8
#define HD     128
#define HID    14336
#define VOC    32000
#define SEQ    2048
#define POS_NEW 2047

// ---------------- scratch (static device mem; no allocations) ----------------
__device__ float g_h   [B*DM];       // embedding / residual stream 1
__device__ float g_xn  [B*DM];       // rmsnorm1 output
__device__ float g_q   [B*DM];
__device__ float g_k   [B*NKV*HD];
__device__ float g_v   [B*NKV*HD];
__device__ float g_pm  [B*NH*32];    // attention partial max
__device__ float g_pl  [B*NH*32];    // attention partial sum
__device__ float g_pacc[B*NH*32*HD]; // attention partial acc
__device__ float g_ao  [B*DM];       // attention output
__device__ float g_acc1[B*DM];       // wo accumulation
__device__ float g_res [B*DM];       // residual stream 2
__device__ float g_xn2 [B*DM];       // rmsnorm2 output
__device__ float g_h1  [B*HID];
__device__ float g_h3  [B*HID];
__device__ float g_ffh [B*HID];
__device__ float g_acc2[B*DM];       // w2 accumulation
__device__ float g_res2[B*DM];
__device__ float g_xn3 [B*DM];       // final rmsnorm output

// ---------------- zero accumulators + output ----------------
__global__ void k_zero(float* __restrict__ out) {
    int i0 = blockIdx.x * blockDim.x + threadIdx.x;
    int st = gridDim.x * blockDim.x;
    for (int i = i0; i < B*VOC; i += st) out[i] = 0.f;
    for (int i = i0; i < B*DM; i += st) { g_q[i] = 0.f; g_acc1[i] = 0.f; g_acc2[i] = 0.f; }
    for (int i = i0; i < B*NKV*HD; i += st) { g_k[i] = 0.f; g_v[i] = 0.f; }
    for (int i = i0; i < B*HID; i += st) { g_h1[i] = 0.f; g_h3[i] = 0.f; }
}

// ---------------- embedding + rmsnorm1 ----------------
__global__ void k_embed(const int* __restrict__ tokens,
                        const float* __restrict__ emb,
                        const float* __restrict__ gamma) {
    int b = blockIdx.x;
    int tok = tokens[b];
    __shared__ float red[256];
    float s = 0.f;
    for (int i = threadIdx.x; i < DM; i += 256) {
        float v = emb[(size_t)tok * DM + i];
        g_h[b*DM + i] = v;
        s += v * v;
    }
    red[threadIdx.x] = s; __syncthreads();
    for (int off = 128; off > 0; off >>= 1) {
        if (threadIdx.x < off) red[threadIdx.x] += red[threadIdx.x + off];
        __syncthreads();
    }
    float scale = 64.0f / sqrtf(red[0]);   // x * sqrt(D)/sqrt(sum x^2)
    for (int i = threadIdx.x; i < DM; i += 256)
        g_xn[b*DM + i] = g_h[b*DM + i] * gamma[i] * scale;
}

// ---------------- residual add + rmsnorm ----------------
__global__ void k_addnorm(const float* __restrict__ acc,
                          const float* __restrict__ res,
                          const float* __restrict__ gamma,
                          float* __restrict__ outres,
                          float* __restrict__ outn) {
    int b = blockIdx.x;
    __shared__ float red[256];
    float s = 0.f;
    for (int i = threadIdx.x; i < DM; i += 256) {
        float t = acc[b*DM + i] + res[b*DM + i];
        outres[b*DM + i] = t;
        s += t * t;
    }
    red[threadIdx.x] = s; __syncthreads();
    for (int off = 128; off > 0; off >>= 1) {
        if (threadIdx.x < off) red[threadIdx.x] += red[threadIdx.x + off];
        __syncthreads();
    }
    float scale = 64.0f / sqrtf(red[0]);
    for (int i = threadIdx.x; i < DM; i += 256)
        outn[b*DM + i] = outres[b*DM + i] * gamma[i] * scale;
}

// ---------------- split-K batched GEMV: Y[8][N] += X[8][K-chunk] @ W ----------------
// 128 threads, 4 cols/thread (512 cols/block), grid = (ceil(N/512), K/BK)
#define ACC4(A, xb) { A.x += w.x*(xb); A.y += w.y*(xb); A.z += w.z*(xb); A.w += w.w*(xb); }

template<int BK>
__global__ void __launch_bounds__(128)
k_gemv(const float* __restrict__ X, const float* __restrict__ W,
       float* __restrict__ Y, int K, int N) {
    __shared__ float xs[BK * 8];   // xs[kk][b]
    int tid = threadIdx.x;
    int k0 = blockIdx.y * BK;
    for (int i = tid; i < BK * 8; i += 128) {
        int b = i / BK, kk = i - b * BK;
        xs[kk * 8 + b] = X[b * K + k0 + kk];
    }
    __syncthreads();

    int n = blockIdx.x * 512 + tid * 4;
    if (n >= N) return;

    const float* wrow = W + (size_t)k0 * N + n;
    const float4* xs4 = (const float4*)xs;
    float4 a0 = make_float4(0,0,0,0), a1 = a0, a2 = a0, a3 = a0;
    float4 a4 = a0, a5 = a0, a6 = a0, a7 = a0;

#pragma unroll 8
    for (int kk = 0; kk < BK; kk++) {
        float4 w = *(const float4*)wrow;
        wrow += N;
        float4 xa = xs4[kk * 2];
        float4 xb = xs4[kk * 2 + 1];
        ACC4(a0, xa.x) ACC4(a1, xa.y) ACC4(a2, xa.z) ACC4(a3, xa.w)
        ACC4(a4, xb.x) ACC4(a5, xb.y) ACC4(a6, xb.z) ACC4(a7, xb.w)
    }

    float4 acc[8] = {a0,a1,a2,a3,a4,a5,a6,a7};
#pragma unroll
    for (int b = 0; b < 8; b++) {
        float* yp = Y + (size_t)b * N + n;
        atomicAdd(yp + 0, acc[b].x);
        atomicAdd(yp + 1, acc[b].y);
        atomicAdd(yp + 2, acc[b].z);
        atomicAdd(yp + 3, acc[b].w);
    }
}

// ---------------- RoPE on q and k (position = 2047) ----------------
__global__ void k_rope() {
    int idx = blockIdx.x * 256 + threadIdx.x;
    if (idx >= B*NH*64 + B*NKV*64) return;   // 16384 + 4096
    float* base;
    int j;
    if (idx < B*NH*64) {
        int b = idx / (NH*64); int r = idx % (NH*64);
        int h = r / 64; j = r % 64;
        base = &g_q[b*DM + h*HD + 2*j];
    } else {
        int t = idx - B*NH*64;
        int b = t / (NKV*64); int r = t % (NKV*64);
        int h = r / 64; j = r % 64;
        base = &g_k[b*NKV*HD + h*HD + 2*j];
    }
    float fe   = (float)(2 * j) * (1.0f / 128.0f);
    float invf = 1.0f / powf(10000.0f, fe);
    float ang  = 2047.0f * invf;
    float c = cosf(ang), s = sinf(ang);
    float x0 = base[0], x1 = base[1];
    base[0] = x0 * c - x1 * s;
    base[1] = x0 * s + x1 * c;
}

// ---------------- attention, flash-decoding splits ----------------
// grid (8 splits, 8 kv, 8 batch), 128 threads (4 warps); warp owns 64 positions,
// 1 warp-wide 512B load per K row / V row, online softmax for the 4 GQA heads.
__global__ void __launch_bounds__(128)
k_attn(const float* __restrict__ ck, const float* __restrict__ cv) {
    int b = blockIdx.z, kv = blockIdx.y, split = blockIdx.x;
    int wid = threadIdx.x >> 5, lane = threadIdx.x & 31;
    int p0 = split * 256 + wid * 64;

    float4 q[4];
#pragma unroll
    for (int h = 0; h < 4; h++)
        q[h] = *(const float4*)&g_q[b*DM + (kv*4 + h)*HD + lane*4];

    float m[4], l[4];
    float4 a[4];
#pragma unroll
    for (int h = 0; h < 4; h++) { m[h] = -1e30f; l[h] = 0.f; a[h] = make_float4(0,0,0,0); }

    const float scale = 0.08838834764831845f;   // 1/sqrt(128)

    for (int p = p0; p < p0 + 64; p++) {
        const float* kptr = (p == POS_NEW) ? &g_k[b*NKV*HD + kv*HD]
                                           : &ck[(((size_t)b*SEQ + p)*NKV + kv)*HD];
        float4 kx = *(const float4*)(kptr + lane*4);
        float s4[4];
#pragma unroll
        for (int h = 0; h < 4; h++)
            s4[h] = q[h].x*kx.x + q[h].y*kx.y + q[h].z*kx.z + q[h].w*kx.w;
#pragma unroll
        for (int off = 16; off; off >>= 1) {
#pragma unroll
            for (int h = 0; h < 4; h++)
                s4[h] += __shfl_xor_sync(0xffffffffu, s4[h], off);
        }
        const float* vptr = (p == POS_NEW) ? &g_v[b*NKV*HD + kv*HD]
                                           : &cv[(((size_t)b*SEQ + p)*NKV + kv)*HD];
        float4 vx = *(const float4*)(vptr + lane*4);
#pragma unroll
        for (int h = 0; h < 4; h++) {
            float sc = s4[h] * scale;
            if (sc > m[h]) {
                float corr = __expf(m[h] - sc);
                l[h] *= corr;
                a[h].x *= corr; a[h].y *= corr; a[h].z *= corr; a[h].w *= corr;
                m[h] = sc;
            }
            float e = __expf(sc - m[h]);
            l[h] += e;
            a[h].x += e * vx.x; a[h].y += e * vx.y;
            a[h].z += e * vx.z; a[h].w += e * vx.w;
        }
    }

    int part = split * 4 + wid;   // 0..31
#pragma unroll
    for (int h = 0; h < 4; h++) {
        int head = kv*4 + h;
        int pi = (b*NH + head)*32 + part;
        if (lane == 0) { g_pm[pi] = m[h]; g_pl[pi] = l[h]; }
        *(float4*)&g_pacc[(size_t)pi*HD + lane*4] = a[h];
    }
}

// ---------------- attention split combine ----------------
__global__ void k_combine() {
    int bh = blockIdx.x;         // b*NH + head
    int d = threadIdx.x;         // 0..127
    float M = -1e30f;
#pragma unroll
    for (int i = 0; i < 32; i++) M = fmaxf(M, g_pm[bh*32 + i]);
    float L = 0.f, o = 0.f;
#pragma unroll
    for (int i = 0; i < 32; i++) {
        float w = __expf(g_pm[bh*32 + i] - M);
        L += g_pl[bh*32 + i] * w;
        o += g_pacc[(size_t)(bh*32 + i)*HD + d] * w;
    }
    g_ao[bh*HD + d] = o / L;     // [b][head*128+d] == [b][DM] layout
}

// ---------------- silu(h1) * h3 ----------------
__global__ void k_silu() {
    int i = blockIdx.x * 256 + threadIdx.x;
    if (i < B*HID) {
        float x = g_h1[i];
        g_ffh[i] = (x / (1.0f + expf(-x))) * g_h3[i];
    }
}

// ---------------- launch ----------------
extern "C" void kernel_launch(void* const* d_in, const int* in_sizes, int n_in,
                              void* d_out, int out_size) {
    const int*   tokens = (const int*)  d_in[0];
    /* d_in[1] = start_pos (fixed 2047, baked in) */
    const float* emb  = (const float*)d_in[2];
    const float* g1   = (const float*)d_in[3];
    const float* g2   = (const float*)d_in[4];
    const float* gf   = (const float*)d_in[5];
    const float* wq   = (const float*)d_in[6];
    const float* wk   = (const float*)d_in[7];
    const float* wv   = (const float*)d_in[8];
    const float* wo   = (const float*)d_in[9];
    const float* w1   = (const float*)d_in[10];
    const float* w2   = (const float*)d_in[11];
    const float* w3   = (const float*)d_in[12];
    const float* wout = (const float*)d_in[13];
    const float* ck   = (const float*)d_in[14];
    const float* cv   = (const float*)d_in[15];
    float* out = (float*)d_out;

    float *p_xn, *p_q, *p_k, *p_v, *p_ao, *p_acc1, *p_h, *p_res, *p_xn2;
    float *p_h1, *p_h3, *p_ffh, *p_acc2, *p_res2, *p_xn3;
    cudaGetSymbolAddress((void**)&p_xn,  g_xn);
    cudaGetSymbolAddress((void**)&p_q,   g_q);
    cudaGetSymbolAddress((void**)&p_k,   g_k);
    cudaGetSymbolAddress((void**)&p_v,   g_v);
    cudaGetSymbolAddress((void**)&p_ao,  g_ao);
    cudaGetSymbolAddress((void**)&p_acc1,g_acc1);
    cudaGetSymbolAddress((void**)&p_h,   g_h);
    cudaGetSymbolAddress((void**)&p_res, g_res);
    cudaGetSymbolAddress((void**)&p_xn2, g_xn2);
    cudaGetSymbolAddress((void**)&p_h1,  g_h1);
    cudaGetSymbolAddress((void**)&p_h3,  g_h3);
    cudaGetSymbolAddress((void**)&p_ffh, g_ffh);
    cudaGetSymbolAddress((void**)&p_acc2,g_acc2);
    cudaGetSymbolAddress((void**)&p_res2,g_res2);
    cudaGetSymbolAddress((void**)&p_xn3, g_xn3);

    k_zero<<<256, 256>>>(out);
    k_embed<<<8, 256>>>(tokens, emb, g1);

    // QKV projections (split-K 32)
    k_gemv<128><<<dim3(8, 32), 128>>>(p_xn, wq, p_q, DM, DM);
    k_gemv<128><<<dim3(2, 32), 128>>>(p_xn, wk, p_k, DM, NKV*HD);
    k_gemv<128><<<dim3(2, 32), 128>>>(p_xn, wv, p_v, DM, NKV*HD);

    k_rope<<<80, 256>>>();
    k_attn<<<dim3(8, 8, 8), 128>>>(ck, cv);
    k_combine<<<B*NH, 128>>>();

    // wo + residual/norm
    k_gemv<128><<<dim3(8, 32), 128>>>(p_ao, wo, p_acc1, DM, DM);
    k_addnorm<<<8, 256>>>(p_acc1, p_h, g2, p_res, p_xn2);

    // FFN
    k_gemv<256><<<dim3(28, 16), 128>>>(p_xn2, w1, p_h1, DM, HID);
    k_gemv<256><<<dim3(28, 16), 128>>>(p_xn2, w3, p_h3, DM, HID);
    k_silu<<<(B*HID + 255)/256, 256>>>();
    k_gemv<448><<<dim3(8, 32), 128>>>(p_ffh, w2, p_acc2, HID, DM);
    k_addnorm<<<8, 256>>>(p_acc2, p_res, gf, p_res2, p_xn3);

    // logits
    k_gemv<512><<<dim3(63, 8), 128>>>(p_xn3, wout, out, DM, VOC);
}

// round 2
// speedup vs baseline: 1.3493x; 1.3493x over previous
#include <cuda_runtime.h>
#include <math.h>

#define B      8
#define DM     4096
#define NH     32
#define NKV    8
#define HD     128
#define HID    14336
#define VOC    32000
#define SEQ    2048
#define POS_NEW 2047

// ---------------- scratch (static device mem; no allocations) ----------------
__device__ float g_h   [B*DM];       // embedding / residual stream 1
__device__ float g_xn  [B*DM];       // rmsnorm1 output
__device__ float g_q   [B*DM];
__device__ float g_k   [B*NKV*HD];
__device__ float g_v   [B*NKV*HD];
__device__ float g_pm  [B*NH*32];    // attention partial max
__device__ float g_pl  [B*NH*32];    // attention partial sum
__device__ float g_pacc[B*NH*32*HD]; // attention partial acc
__device__ float g_ao  [B*DM];       // attention output
__device__ float g_acc1[B*DM];       // wo accumulation
__device__ float g_res [B*DM];       // residual stream 2
__device__ float g_xn2 [B*DM];       // rmsnorm2 output
__device__ float g_h1  [B*HID];
__device__ float g_h3  [B*HID];
__device__ float g_ffh [B*HID];
__device__ float g_acc2[B*DM];       // w2 accumulation
__device__ float g_res2[B*DM];
__device__ float g_xn3 [B*DM];       // final rmsnorm output

// ---------------- zero accumulators + output ----------------
__global__ void k_zero(float* __restrict__ out) {
    int i0 = blockIdx.x * blockDim.x + threadIdx.x;
    int st = gridDim.x * blockDim.x;
    for (int i = i0; i < B*VOC; i += st) out[i] = 0.f;
    for (int i = i0; i < B*DM; i += st) { g_q[i] = 0.f; g_acc1[i] = 0.f; g_acc2[i] = 0.f; }
    for (int i = i0; i < B*NKV*HD; i += st) { g_k[i] = 0.f; g_v[i] = 0.f; }
    for (int i = i0; i < B*HID; i += st) { g_h1[i] = 0.f; g_h3[i] = 0.f; }
}

// ---------------- embedding + rmsnorm1 ----------------
__global__ void k_embed(const int* __restrict__ tokens,
                        const float* __restrict__ emb,
                        const float* __restrict__ gamma) {
    int b = blockIdx.x;
    int tok = tokens[b];
    __shared__ float red[256];
    float s = 0.f;
    for (int i = threadIdx.x; i < DM; i += 256) {
        float v = emb[(size_t)tok * DM + i];
        g_h[b*DM + i] = v;
        s += v * v;
    }
    red[threadIdx.x] = s; __syncthreads();
    for (int off = 128; off > 0; off >>= 1) {
        if (threadIdx.x < off) red[threadIdx.x] += red[threadIdx.x + off];
        __syncthreads();
    }
    float scale = 64.0f / sqrtf(red[0]);
    for (int i = threadIdx.x; i < DM; i += 256)
        g_xn[b*DM + i] = g_h[b*DM + i] * gamma[i] * scale;
}

// ---------------- residual add + rmsnorm ----------------
__global__ void k_addnorm(const float* __restrict__ acc,
                          const float* __restrict__ res,
                          const float* __restrict__ gamma,
                          float* __restrict__ outres,
                          float* __restrict__ outn) {
    int b = blockIdx.x;
    __shared__ float red[256];
    float s = 0.f;
    for (int i = threadIdx.x; i < DM; i += 256) {
        float t = acc[b*DM + i] + res[b*DM + i];
        outres[b*DM + i] = t;
        s += t * t;
    }
    red[threadIdx.x] = s; __syncthreads();
    for (int off = 128; off > 0; off >>= 1) {
        if (threadIdx.x < off) red[threadIdx.x] += red[threadIdx.x + off];
        __syncthreads();
    }
    float scale = 64.0f / sqrtf(red[0]);
    for (int i = threadIdx.x; i < DM; i += 256)
        outn[b*DM + i] = outres[b*DM + i] * gamma[i] * scale;
}

// =====================================================================
// GEMV v2: block = 512 threads (16 warps), 128 output cols per block.
// Warp w handles RPW rows of the block's K-chunk (chunk = RPW*16 rows).
// Lane handles 4 consecutive cols (float4 weight loads, 512B/warp/row).
// Warp partials reduced via smem atomics, then one REDG per output.
// grid = (N/128, K/(RPW*16), fuse) ; z selects (X,W,Y) pair.
// =====================================================================
#define FMA4(A, wv, xb) { A.x += wv.x*(xb); A.y += wv.y*(xb); A.z += wv.z*(xb); A.w += wv.w*(xb); }

template<int RPW>
__global__ void __launch_bounds__(512, 1)
k_gemv2(const float* __restrict__ X0, const float* __restrict__ W0, float* __restrict__ Y0,
        const float* __restrict__ X1, const float* __restrict__ W1, float* __restrict__ Y1,
        int K, int N) {
    constexpr int ROWS = RPW * 16;
    extern __shared__ float sm[];
    float* xs   = sm;               // [ROWS][8]  x values, row-major, batch fastest
    float* sacc = sm + ROWS * 8;    // [8][128]   block accumulator

    const float* X = blockIdx.z ? X1 : X0;
    const float* W = blockIdx.z ? W1 : W0;
    float*       Y = blockIdx.z ? Y1 : Y0;

    int tid = threadIdx.x;
    int k0  = blockIdx.y * ROWS;
    int nb  = blockIdx.x * 128;

    sacc[tid] = 0.f; sacc[tid + 512] = 0.f;

    for (int i = tid; i < ROWS * 8; i += 512) {
        int b = i / ROWS, r = i - b * ROWS;
        xs[r * 8 + b] = X[b * K + k0 + r];
    }
    __syncthreads();

    int w = tid >> 5, lane = tid & 31;
    int r0 = w * RPW;
    const float* wp = W + (size_t)(k0 + r0) * N + nb + lane * 4;

    float4 acc[8];
#pragma unroll
    for (int b = 0; b < 8; b++) acc[b] = make_float4(0, 0, 0, 0);

    for (int r = 0; r < RPW; r += 8) {
        float4 wreg[8];
#pragma unroll
        for (int u = 0; u < 8; u++)
            wreg[u] = *(const float4*)(wp + (size_t)u * N);
        wp += (size_t)8 * N;
#pragma unroll
        for (int u = 0; u < 8; u++) {
            const float* xr = &xs[(r0 + r + u) * 8];
            float4 xa = *(const float4*)xr;
            float4 xb = *(const float4*)(xr + 4);
            float4 wv = wreg[u];
            FMA4(acc[0], wv, xa.x) FMA4(acc[1], wv, xa.y)
            FMA4(acc[2], wv, xa.z) FMA4(acc[3], wv, xa.w)
            FMA4(acc[4], wv, xb.x) FMA4(acc[5], wv, xb.y)
            FMA4(acc[6], wv, xb.z) FMA4(acc[7], wv, xb.w)
        }
    }

#pragma unroll
    for (int b = 0; b < 8; b++) {
        float* s = &sacc[b * 128 + lane * 4];
        atomicAdd(s + 0, acc[b].x);
        atomicAdd(s + 1, acc[b].y);
        atomicAdd(s + 2, acc[b].z);
        atomicAdd(s + 3, acc[b].w);
    }
    __syncthreads();

#pragma unroll
    for (int i = tid; i < 1024; i += 512) {
        int b = i >> 7, c = i & 127;
        atomicAdd(&Y[(size_t)b * N + nb + c], sacc[i]);
    }
}

// ---------------- RoPE on q and k (position = 2047) ----------------
__global__ void k_rope() {
    int idx = blockIdx.x * 256 + threadIdx.x;
    if (idx >= B*NH*64 + B*NKV*64) return;
    float* base;
    int j;
    if (idx < B*NH*64) {
        int b = idx / (NH*64); int r = idx % (NH*64);
        int h = r / 64; j = r % 64;
        base = &g_q[b*DM + h*HD + 2*j];
    } else {
        int t = idx - B*NH*64;
        int b = t / (NKV*64); int r = t % (NKV*64);
        int h = r / 64; j = r % 64;
        base = &g_k[b*NKV*HD + h*HD + 2*j];
    }
    float fe   = (float)(2 * j) * (1.0f / 128.0f);
    float invf = 1.0f / powf(10000.0f, fe);
    float ang  = 2047.0f * invf;
    float c = cosf(ang), s = sinf(ang);
    float x0 = base[0], x1 = base[1];
    base[0] = x0 * c - x1 * s;
    base[1] = x0 * s + x1 * c;
}

// ---------------- attention, flash-decoding splits (with K/V prefetch) ----------------
__global__ void __launch_bounds__(128)
k_attn(const float* __restrict__ ck, const float* __restrict__ cv) {
    int b = blockIdx.z, kv = blockIdx.y, split = blockIdx.x;
    int wid = threadIdx.x >> 5, lane = threadIdx.x & 31;
    int p0 = split * 256 + wid * 64;

    float4 q[4];
#pragma unroll
    for (int h = 0; h < 4; h++)
        q[h] = *(const float4*)&g_q[b*DM + (kv*4 + h)*HD + lane*4];

    float m[4], l[4];
    float4 a[4];
#pragma unroll
    for (int h = 0; h < 4; h++) { m[h] = -1e30f; l[h] = 0.f; a[h] = make_float4(0,0,0,0); }

    const float scale = 0.08838834764831845f;

    const float* kp0 = (p0 == POS_NEW) ? &g_k[b*NKV*HD + kv*HD]
                                       : &ck[(((size_t)b*SEQ + p0)*NKV + kv)*HD];
    const float* vp0 = (p0 == POS_NEW) ? &g_v[b*NKV*HD + kv*HD]
                                       : &cv[(((size_t)b*SEQ + p0)*NKV + kv)*HD];
    float4 kx = *(const float4*)(kp0 + lane*4);
    float4 vx = *(const float4*)(vp0 + lane*4);

    for (int p = p0; p < p0 + 64; p++) {
        float4 kn = make_float4(0,0,0,0), vn = kn;
        if (p + 1 < p0 + 64) {
            int pn = p + 1;
            const float* kptr = (pn == POS_NEW) ? &g_k[b*NKV*HD + kv*HD]
                                                : &ck[(((size_t)b*SEQ + pn)*NKV + kv)*HD];
            const float* vptr = (pn == POS_NEW) ? &g_v[b*NKV*HD + kv*HD]
                                                : &cv[(((size_t)b*SEQ + pn)*NKV + kv)*HD];
            kn = *(const float4*)(kptr + lane*4);
            vn = *(const float4*)(vptr + lane*4);
        }
        float s4[4];
#pragma unroll
        for (int h = 0; h < 4; h++)
            s4[h] = q[h].x*kx.x + q[h].y*kx.y + q[h].z*kx.z + q[h].w*kx.w;
#pragma unroll
        for (int off = 16; off; off >>= 1) {
#pragma unroll
            for (int h = 0; h < 4; h++)
                s4[h] += __shfl_xor_sync(0xffffffffu, s4[h], off);
        }
#pragma unroll
        for (int h = 0; h < 4; h++) {
            float sc = s4[h] * scale;
            if (sc > m[h]) {
                float corr = __expf(m[h] - sc);
                l[h] *= corr;
                a[h].x *= corr; a[h].y *= corr; a[h].z *= corr; a[h].w *= corr;
                m[h] = sc;
            }
            float e = __expf(sc - m[h]);
            l[h] += e;
            a[h].x += e * vx.x; a[h].y += e * vx.y;
            a[h].z += e * vx.z; a[h].w += e * vx.w;
        }
        kx = kn; vx = vn;
    }

    int part = split * 4 + wid;
#pragma unroll
    for (int h = 0; h < 4; h++) {
        int head = kv*4 + h;
        int pi = (b*NH + head)*32 + part;
        if (lane == 0) { g_pm[pi] = m[h]; g_pl[pi] = l[h]; }
        *(float4*)&g_pacc[(size_t)pi*HD + lane*4] = a[h];
    }
}

// ---------------- attention split combine ----------------
__global__ void k_combine() {
    int bh = blockIdx.x;
    int d = threadIdx.x;
    float M = -1e30f;
#pragma unroll
    for (int i = 0; i < 32; i++) M = fmaxf(M, g_pm[bh*32 + i]);
    float L = 0.f, o = 0.f;
#pragma unroll
    for (int i = 0; i < 32; i++) {
        float w = __expf(g_pm[bh*32 + i] - M);
        L += g_pl[bh*32 + i] * w;
        o += g_pacc[(size_t)(bh*32 + i)*HD + d] * w;
    }
    g_ao[bh*HD + d] = o / L;
}

// ---------------- silu(h1) * h3 ----------------
__global__ void k_silu() {
    int i = blockIdx.x * 256 + threadIdx.x;
    if (i < B*HID) {
        float x = g_h1[i];
        g_ffh[i] = (x / (1.0f + expf(-x))) * g_h3[i];
    }
}

// ---------------- launch ----------------
static inline int smem_bytes(int rpw) { return (rpw * 16 * 8 + 1024) * (int)sizeof(float); }

extern "C" void kernel_launch(void* const* d_in, const int* in_sizes, int n_in,
                              void* d_out, int out_size) {
    const int*   tokens = (const int*)  d_in[0];
    const float* emb  = (const float*)d_in[2];
    const float* g1   = (const float*)d_in[3];
    const float* g2   = (const float*)d_in[4];
    const float* gf   = (const float*)d_in[5];
    const float* wq   = (const float*)d_in[6];
    const float* wk   = (const float*)d_in[7];
    const float* wv   = (const float*)d_in[8];
    const float* wo   = (const float*)d_in[9];
    const float* w1   = (const float*)d_in[10];
    const float* w2   = (const float*)d_in[11];
    const float* w3   = (const float*)d_in[12];
    const float* wout = (const float*)d_in[13];
    const float* ck   = (const float*)d_in[14];
    const float* cv   = (const float*)d_in[15];
    float* out = (float*)d_out;

    float *p_xn, *p_q, *p_k, *p_v, *p_ao, *p_acc1, *p_h, *p_res, *p_xn2;
    float *p_h1, *p_h3, *p_ffh, *p_acc2, *p_res2, *p_xn3;
    cudaGetSymbolAddress((void**)&p_xn,  g_xn);
    cudaGetSymbolAddress((void**)&p_q,   g_q);
    cudaGetSymbolAddress((void**)&p_k,   g_k);
    cudaGetSymbolAddress((void**)&p_v,   g_v);
    cudaGetSymbolAddress((void**)&p_ao,  g_ao);
    cudaGetSymbolAddress((void**)&p_acc1,g_acc1);
    cudaGetSymbolAddress((void**)&p_h,   g_h);
    cudaGetSymbolAddress((void**)&p_res, g_res);
    cudaGetSymbolAddress((void**)&p_xn2, g_xn2);
    cudaGetSymbolAddress((void**)&p_h1,  g_h1);
    cudaGetSymbolAddress((void**)&p_h3,  g_h3);
    cudaGetSymbolAddress((void**)&p_ffh, g_ffh);
    cudaGetSymbolAddress((void**)&p_acc2,g_acc2);
    cudaGetSymbolAddress((void**)&p_res2,g_res2);
    cudaGetSymbolAddress((void**)&p_xn3, g_xn3);

    // opt-in to >48KB dynamic smem for the big-chunk instantiations
    cudaFuncSetAttribute(k_gemv2<112>, cudaFuncAttributeMaxDynamicSharedMemorySize, smem_bytes(112));
    cudaFuncSetAttribute(k_gemv2<128>, cudaFuncAttributeMaxDynamicSharedMemorySize, smem_bytes(128));

    k_zero<<<256, 256>>>(out);
    k_embed<<<8, 256>>>(tokens, emb, g1);

    // QKV: wq (N=4096, 8 splits of 512 rows) ; wk+wv fused (N=1024, 16 splits of 256 rows)
    k_gemv2<32><<<dim3(32, 8, 1), 512, smem_bytes(32)>>>(p_xn, wq, p_q, p_xn, wq, p_q, DM, DM);
    k_gemv2<16><<<dim3(8, 16, 2), 512, smem_bytes(16)>>>(p_xn, wk, p_k, p_xn, wv, p_v, DM, NKV*HD);

    k_rope<<<80, 256>>>();
    k_attn<<<dim3(8, 8, 8), 128>>>(ck, cv);
    k_combine<<<B*NH, 128>>>();

    // wo + residual/norm
    k_gemv2<32><<<dim3(32, 8, 1), 512, smem_bytes(32)>>>(p_ao, wo, p_acc1, p_ao, wo, p_acc1, DM, DM);
    k_addnorm<<<8, 256>>>(p_acc1, p_h, g2, p_res, p_xn2);

    // FFN: w1+w3 fused (N=14336, 4 splits of 1024 rows), w2 (K=14336, 8 splits of 1792 rows)
    k_gemv2<64><<<dim3(112, 4, 2), 512, smem_bytes(64)>>>(p_xn2, w1, p_h1, p_xn2, w3, p_h3, DM, HID);
    k_silu<<<(B*HID + 255)/256, 256>>>();
    k_gemv2<112><<<dim3(32, 8, 1), 512, smem_bytes(112)>>>(p_ffh, w2, p_acc2, p_ffh, w2, p_acc2, HID, DM);
    k_addnorm<<<8, 256>>>(p_acc2, p_res, gf, p_res2, p_xn3);

    // logits: N=32000, 2 splits of 2048 rows
    k_gemv2<128><<<dim3(250, 2, 1), 512, smem_bytes(128)>>>(p_xn3, wout, out, p_xn3, wout, out, DM, VOC);
}

// round 3
// speedup vs baseline: 1.6587x; 1.2293x over previous
#include <cuda_runtime.h>
#include <math.h>

#define B      8
#define DM     4096
#define NH     32
#define NKV    8
#define HD     128
#define HID    14336
#define VOC    32000
#define SEQ    2048
#define POS_NEW 2047
#define NSPLIT 16            // attention kv splits

// ---------------- scratch (static device mem; no allocations) ----------------
__device__ float g_h   [B*DM];
__device__ float g_xn  [B*DM];
__device__ float g_q   [B*DM];
__device__ float g_k   [B*NKV*HD];
__device__ float g_v   [B*NKV*HD];
__device__ float g_pm  [B*NH*64];
__device__ float g_pl  [B*NH*64];
__device__ float g_pacc[B*NH*64*HD];
__device__ float g_ao  [B*DM];
__device__ float g_acc1[B*DM];
__device__ float g_res [B*DM];
__device__ float g_xn2 [B*DM];
__device__ float g_h1  [B*HID];
__device__ float g_h3  [B*HID];
__device__ float g_ffh [B*HID];
__device__ float g_acc2[B*DM];
__device__ float g_res2[B*DM];
__device__ float g_xn3 [B*DM];

// ---------------- zero atomic-accumulated buffers ----------------
__global__ void k_zero() {
    int i0 = blockIdx.x * blockDim.x + threadIdx.x;
    int st = gridDim.x * blockDim.x;
    for (int i = i0; i < B*DM; i += st) { g_q[i] = 0.f; g_acc1[i] = 0.f; g_acc2[i] = 0.f; }
    for (int i = i0; i < B*NKV*HD; i += st) { g_k[i] = 0.f; g_v[i] = 0.f; }
    for (int i = i0; i < B*HID; i += st) { g_h1[i] = 0.f; g_h3[i] = 0.f; }
}

// ---------------- embedding + rmsnorm1 ----------------
__global__ void k_embed(const int* __restrict__ tokens,
                        const float* __restrict__ emb,
                        const float* __restrict__ gamma) {
    int b = blockIdx.x;
    int tok = tokens[b];
    __shared__ float red[256];
    float s = 0.f;
    for (int i = threadIdx.x; i < DM; i += 256) {
        float v = emb[(size_t)tok * DM + i];
        g_h[b*DM + i] = v;
        s += v * v;
    }
    red[threadIdx.x] = s; __syncthreads();
    for (int off = 128; off > 0; off >>= 1) {
        if (threadIdx.x < off) red[threadIdx.x] += red[threadIdx.x + off];
        __syncthreads();
    }
    float scale = 64.0f / sqrtf(red[0]);
    for (int i = threadIdx.x; i < DM; i += 256)
        g_xn[b*DM + i] = g_h[b*DM + i] * gamma[i] * scale;
}

// ---------------- residual add + rmsnorm ----------------
__global__ void k_addnorm(const float* __restrict__ acc,
                          const float* __restrict__ res,
                          const float* __restrict__ gamma,
                          float* __restrict__ outres,
                          float* __restrict__ outn) {
    int b = blockIdx.x;
    __shared__ float red[256];
    float s = 0.f;
    for (int i = threadIdx.x; i < DM; i += 256) {
        float t = acc[b*DM + i] + res[b*DM + i];
        outres[b*DM + i] = t;
        s += t * t;
    }
    red[threadIdx.x] = s; __syncthreads();
    for (int off = 128; off > 0; off >>= 1) {
        if (threadIdx.x < off) red[threadIdx.x] += red[threadIdx.x + off];
        __syncthreads();
    }
    float scale = 64.0f / sqrtf(red[0]);
    for (int i = threadIdx.x; i < DM; i += 256)
        outn[b*DM + i] = outres[b*DM + i] * gamma[i] * scale;
}

// =====================================================================
// GEMV v3: 512 threads (16 warps), 128 cols/block, warp split-K inside
// the block (warp owns RPW rows). f32x2 packed FMAs (batch pairs in the
// two lanes), double-buffered 4-row weight prefetch, STS.128 per-warp
// epilogue slices + tree reduction (no smem atomics).
// =====================================================================
__device__ __forceinline__ unsigned long long dup2(float w) {
    unsigned long long r;
    asm("mov.b64 %0, {%1, %1};" : "=l"(r) : "f"(w));
    return r;
}
__device__ __forceinline__ void fma2(unsigned long long& c, unsigned long long a,
                                     unsigned long long x) {
    asm("fma.rn.f32x2 %0, %1, %2, %0;" : "+l"(c) : "l"(a), "l"(x));
}
__device__ __forceinline__ float2 unpk(unsigned long long v) {
    float2 f;
    asm("mov.b64 {%0, %1}, %2;" : "=f"(f.x), "=f"(f.y) : "l"(v));
    return f;
}

template<int RPW>
__global__ void __launch_bounds__(512, 1)
k_gemv3(const float* __restrict__ X0, const float* __restrict__ W0, float* __restrict__ Y0,
        const float* __restrict__ X1, const float* __restrict__ W1, float* __restrict__ Y1,
        int K, int N) {
    constexpr int ROWS = RPW * 16;
    extern __shared__ float sm[];
    float* xs = sm;                 // [ROWS][8], batch fastest (b-pairs adjacent)
    float* sw = sm + ROWS * 8;      // [16 warps][8 batch][128 cols]

    const float* X = blockIdx.z ? X1 : X0;
    const float* W = blockIdx.z ? W1 : W0;
    float*       Y = blockIdx.z ? Y1 : Y0;

    int tid = threadIdx.x;
    int k0  = blockIdx.y * ROWS;
    int nb  = blockIdx.x * 128;

    for (int i = tid; i < ROWS * 8; i += 512) {
        int b = i / ROWS, r = i - b * ROWS;
        xs[r * 8 + b] = X[b * K + k0 + r];
    }
    __syncthreads();

    int w = tid >> 5, lane = tid & 31;
    int r0 = w * RPW;
    const float* wp = W + (size_t)(k0 + r0) * N + nb + lane * 4;

    unsigned long long acc[4][4];   // [col c][batch-pair p]
#pragma unroll
    for (int c = 0; c < 4; c++)
#pragma unroll
        for (int p = 0; p < 4; p++) acc[c][p] = 0ull;

    float4 buf0[4], buf1[4];
#pragma unroll
    for (int u = 0; u < 4; u++) buf0[u] = *(const float4*)(wp + (size_t)u * N);
    wp += (size_t)4 * N;

#define CONSUME(BUF, BASE)                                                     \
    {                                                                          \
        _Pragma("unroll")                                                      \
        for (int u = 0; u < 4; u++) {                                          \
            const float* xrow = &xs[(r0 + (BASE) + u) * 8];                    \
            ulonglong2 xa = *(const ulonglong2*)xrow;                          \
            ulonglong2 xb = *(const ulonglong2*)(xrow + 4);                    \
            unsigned long long xp[4] = {xa.x, xa.y, xb.x, xb.y};               \
            float4 wv = BUF[u];                                                \
            unsigned long long wd[4] = {dup2(wv.x), dup2(wv.y),                \
                                        dup2(wv.z), dup2(wv.w)};               \
            _Pragma("unroll")                                                  \
            for (int c = 0; c < 4; c++)                                        \
                _Pragma("unroll")                                              \
                for (int p = 0; p < 4; p++) fma2(acc[c][p], wd[c], xp[p]);     \
        }                                                                      \
    }

#pragma unroll 1
    for (int r = 0; r < RPW; r += 8) {
#pragma unroll
        for (int u = 0; u < 4; u++) buf1[u] = *(const float4*)(wp + (size_t)u * N);
        wp += (size_t)4 * N;
        CONSUME(buf0, r)
        if (r + 8 < RPW) {
#pragma unroll
            for (int u = 0; u < 4; u++) buf0[u] = *(const float4*)(wp + (size_t)u * N);
            wp += (size_t)4 * N;
        }
        CONSUME(buf1, r + 4)
    }
#undef CONSUME

    // per-warp slice write (STS.128, conflict-free)
#pragma unroll
    for (int p = 0; p < 4; p++) {
        float2 c0 = unpk(acc[0][p]), c1 = unpk(acc[1][p]);
        float2 c2 = unpk(acc[2][p]), c3 = unpk(acc[3][p]);
        float4 lo = make_float4(c0.x, c1.x, c2.x, c3.x);   // batch 2p
        float4 hi = make_float4(c0.y, c1.y, c2.y, c3.y);   // batch 2p+1
        *(float4*)&sw[(w * 8 + 2*p    ) * 128 + lane * 4] = lo;
        *(float4*)&sw[(w * 8 + 2*p + 1) * 128 + lane * 4] = hi;
    }
    __syncthreads();

    bool single = (gridDim.y == 1);
#pragma unroll
    for (int o = tid; o < 1024; o += 512) {
        float s = 0.f;
#pragma unroll
        for (int ww = 0; ww < 16; ww++) s += sw[ww * 1024 + o];
        int b = o >> 7, c = o & 127;
        float* yp = &Y[(size_t)b * N + nb + c];
        if (single) *yp = s;
        else        atomicAdd(yp, s);
    }
}

// ---------------- RoPE on q and k (position = 2047) ----------------
__global__ void k_rope() {
    int idx = blockIdx.x * 256 + threadIdx.x;
    if (idx >= B*NH*64 + B*NKV*64) return;
    float* base;
    int j;
    if (idx < B*NH*64) {
        int b = idx / (NH*64); int r = idx % (NH*64);
        int h = r / 64; j = r % 64;
        base = &g_q[b*DM + h*HD + 2*j];
    } else {
        int t = idx - B*NH*64;
        int b = t / (NKV*64); int r = t % (NKV*64);
        int h = r / 64; j = r % 64;
        base = &g_k[b*NKV*HD + h*HD + 2*j];
    }
    float fe   = (float)(2 * j) * (1.0f / 128.0f);
    float invf = 1.0f / powf(10000.0f, fe);
    float ang  = 2047.0f * invf;
    float c = cosf(ang), s = sinf(ang);
    float x0 = base[0], x1 = base[1];
    base[0] = x0 * c - x1 * s;
    base[1] = x0 * s + x1 * c;
}

// ---------------- attention: 16 splits, 4-position batched K/V loads ----------------
__global__ void __launch_bounds__(128)
k_attn(const float* __restrict__ ck, const float* __restrict__ cv) {
    int b = blockIdx.z, kv = blockIdx.y, split = blockIdx.x;
    int wid = threadIdx.x >> 5, lane = threadIdx.x & 31;
    int p0 = split * 128 + wid * 32;

    float4 q[4];
#pragma unroll
    for (int h = 0; h < 4; h++)
        q[h] = *(const float4*)&g_q[b*DM + (kv*4 + h)*HD + lane*4];

    float m[4], l[4];
    float4 a[4];
#pragma unroll
    for (int h = 0; h < 4; h++) { m[h] = -1e30f; l[h] = 0.f; a[h] = make_float4(0,0,0,0); }

    const float scale = 0.08838834764831845f;

    for (int pc = 0; pc < 32; pc += 4) {
        float4 kxs[4], vxs[4];
#pragma unroll
        for (int j = 0; j < 4; j++) {
            int p = p0 + pc + j;
            const float* kp = (p == POS_NEW) ? &g_k[b*NKV*HD + kv*HD]
                                             : &ck[(((size_t)b*SEQ + p)*NKV + kv)*HD];
            kxs[j] = *(const float4*)(kp + lane*4);
        }
#pragma unroll
        for (int j = 0; j < 4; j++) {
            int p = p0 + pc + j;
            const float* vp = (p == POS_NEW) ? &g_v[b*NKV*HD + kv*HD]
                                             : &cv[(((size_t)b*SEQ + p)*NKV + kv)*HD];
            vxs[j] = *(const float4*)(vp + lane*4);
        }
#pragma unroll
        for (int j = 0; j < 4; j++) {
            float4 kx = kxs[j];
            float s4[4];
#pragma unroll
            for (int h = 0; h < 4; h++)
                s4[h] = q[h].x*kx.x + q[h].y*kx.y + q[h].z*kx.z + q[h].w*kx.w;
#pragma unroll
            for (int off = 16; off; off >>= 1) {
#pragma unroll
                for (int h = 0; h < 4; h++)
                    s4[h] += __shfl_xor_sync(0xffffffffu, s4[h], off);
            }
            float4 vx = vxs[j];
#pragma unroll
            for (int h = 0; h < 4; h++) {
                float sc = s4[h] * scale;
                if (sc > m[h]) {
                    float corr = __expf(m[h] - sc);
                    l[h] *= corr;
                    a[h].x *= corr; a[h].y *= corr; a[h].z *= corr; a[h].w *= corr;
                    m[h] = sc;
                }
                float e = __expf(sc - m[h]);
                l[h] += e;
                a[h].x += e * vx.x; a[h].y += e * vx.y;
                a[h].z += e * vx.z; a[h].w += e * vx.w;
            }
        }
    }

    int part = split * 4 + wid;   // 0..63
#pragma unroll
    for (int h = 0; h < 4; h++) {
        int head = kv*4 + h;
        int pi = (b*NH + head)*64 + part;
        if (lane == 0) { g_pm[pi] = m[h]; g_pl[pi] = l[h]; }
        *(float4*)&g_pacc[(size_t)pi*HD + lane*4] = a[h];
    }
}

// ---------------- attention split combine (64 partials) ----------------
__global__ void k_combine() {
    int bh = blockIdx.x;
    int d = threadIdx.x;
    float M = -1e30f;
#pragma unroll
    for (int i = 0; i < 64; i++) M = fmaxf(M, g_pm[bh*64 + i]);
    float L = 0.f, o = 0.f;
#pragma unroll
    for (int i = 0; i < 64; i++) {
        float w = __expf(g_pm[bh*64 + i] - M);
        L += g_pl[bh*64 + i] * w;
        o += g_pacc[(size_t)(bh*64 + i)*HD + d] * w;
    }
    g_ao[bh*HD + d] = o / L;
}

// ---------------- silu(h1) * h3 ----------------
__global__ void k_silu() {
    int i = blockIdx.x * 256 + threadIdx.x;
    if (i < B*HID) {
        float x = g_h1[i];
        g_ffh[i] = (x / (1.0f + expf(-x))) * g_h3[i];
    }
}

// ---------------- launch ----------------
static inline int smem_bytes(int rpw) { return rpw * 16 * 8 * (int)sizeof(float) + 65536; }

extern "C" void kernel_launch(void* const* d_in, const int* in_sizes, int n_in,
                              void* d_out, int out_size) {
    const int*   tokens = (const int*)  d_in[0];
    const float* emb  = (const float*)d_in[2];
    const float* g1   = (const float*)d_in[3];
    const float* g2   = (const float*)d_in[4];
    const float* gf   = (const float*)d_in[5];
    const float* wq   = (const float*)d_in[6];
    const float* wk   = (const float*)d_in[7];
    const float* wv   = (const float*)d_in[8];
    const float* wo   = (const float*)d_in[9];
    const float* w1   = (const float*)d_in[10];
    const float* w2   = (const float*)d_in[11];
    const float* w3   = (const float*)d_in[12];
    const float* wout = (const float*)d_in[13];
    const float* ck   = (const float*)d_in[14];
    const float* cv   = (const float*)d_in[15];
    float* out = (float*)d_out;

    float *p_xn, *p_q, *p_k, *p_v, *p_ao, *p_acc1, *p_h, *p_res, *p_xn2;
    float *p_h1, *p_h3, *p_ffh, *p_acc2, *p_res2, *p_xn3;
    cudaGetSymbolAddress((void**)&p_xn,  g_xn);
    cudaGetSymbolAddress((void**)&p_q,   g_q);
    cudaGetSymbolAddress((void**)&p_k,   g_k);
    cudaGetSymbolAddress((void**)&p_v,   g_v);
    cudaGetSymbolAddress((void**)&p_ao,  g_ao);
    cudaGetSymbolAddress((void**)&p_acc1,g_acc1);
    cudaGetSymbolAddress((void**)&p_h,   g_h);
    cudaGetSymbolAddress((void**)&p_res, g_res);
    cudaGetSymbolAddress((void**)&p_xn2, g_xn2);
    cudaGetSymbolAddress((void**)&p_h1,  g_h1);
    cudaGetSymbolAddress((void**)&p_h3,  g_h3);
    cudaGetSymbolAddress((void**)&p_ffh, g_ffh);
    cudaGetSymbolAddress((void**)&p_acc2,g_acc2);
    cudaGetSymbolAddress((void**)&p_res2,g_res2);
    cudaGetSymbolAddress((void**)&p_xn3, g_xn3);

    cudaFuncSetAttribute(k_gemv3<16>,  cudaFuncAttributeMaxDynamicSharedMemorySize, smem_bytes(16));
    cudaFuncSetAttribute(k_gemv3<32>,  cudaFuncAttributeMaxDynamicSharedMemorySize, smem_bytes(32));
    cudaFuncSetAttribute(k_gemv3<112>, cudaFuncAttributeMaxDynamicSharedMemorySize, smem_bytes(112));
    cudaFuncSetAttribute(k_gemv3<256>, cudaFuncAttributeMaxDynamicSharedMemorySize, smem_bytes(256));

    k_zero<<<256, 256>>>();
    k_embed<<<8, 256>>>(tokens, emb, g1);

    // QKV: wq (8 K-splits of 512) ; wk+wv fused (16 K-splits of 256)
    k_gemv3<32><<<dim3(32, 8, 1), 512, smem_bytes(32)>>>(p_xn, wq, p_q, p_xn, wq, p_q, DM, DM);
    k_gemv3<16><<<dim3(8, 16, 2), 512, smem_bytes(16)>>>(p_xn, wk, p_k, p_xn, wv, p_v, DM, NKV*HD);

    k_rope<<<80, 256>>>();
    k_attn<<<dim3(NSPLIT, 8, 8), 128>>>(ck, cv);
    k_combine<<<B*NH, 128>>>();

    // wo + residual/norm
    k_gemv3<32><<<dim3(32, 8, 1), 512, smem_bytes(32)>>>(p_ao, wo, p_acc1, p_ao, wo, p_acc1, DM, DM);
    k_addnorm<<<8, 256>>>(p_acc1, p_h, g2, p_res, p_xn2);

    // FFN: w1+w3 fused (8 K-splits of 512) ; w2 (8 K-splits of 1792)
    k_gemv3<32><<<dim3(112, 8, 2), 512, smem_bytes(32)>>>(p_xn2, w1, p_h1, p_xn2, w3, p_h3, DM, HID);
    k_silu<<<(B*HID + 255)/256, 256>>>();
    k_gemv3<112><<<dim3(32, 8, 1), 512, smem_bytes(112)>>>(p_ffh, w2, p_acc2, p_ffh, w2, p_acc2, HID, DM);
    k_addnorm<<<8, 256>>>(p_acc2, p_res, gf, p_res2, p_xn3);

    // logits: single K-chunk (RPW=256), plain stores, no zero/atomics
    k_gemv3<256><<<dim3(250, 1, 1), 512, smem_bytes(256)>>>(p_xn3, wout, out, p_xn3, wout, out, DM, VOC);
}